// round 3
// baseline (speedup 1.0000x reference)
#include <cuda_runtime.h>
#include <math.h>

#define NB    16
#define PTOT  1024
#define CD    256
#define HND   512
#define SEQL  20
#define MROWS (NB*PTOT)        /* 16384 */
#define KCONV 2304             /* 9 taps * 256 ch */

/* ---------------- scratch (device globals; no allocation allowed) -------- */
__device__ float g_featT [MROWS*CD];      /* state, [n][p][c] */
__device__ float g_base  [MROWS*CD];      /* precomputed spatial+hn conv contribution */
__device__ float g_t     [MROWS*CD];
__device__ float g_fea   [MROWS*CD];
__device__ float g_s1    [MROWS*CD];      /* traw / fearaw / f2raw */
__device__ float g_s2    [MROWS*CD];      /* attn out / mlp hidden */
__device__ float g_kv    [MROWS*2*CD];    /* kh | vv */
__device__ float g_wConvT[KCONV*CD];      /* [tap*256+c][o] */
__device__ float g_wkvT  [CD*2*CD];       /* [c][o2], rows 256..767 of in_proj_w */
__device__ float g_woT   [CD*CD];
__device__ float g_w1T   [CD*CD];
__device__ float g_w2T   [CD*CD];
__device__ float g_hnTap [NB*CD*9];
__device__ float g_sconv [PTOT*CD];
__device__ float g_qhall [SEQL*NB*CD];
__device__ float g_qall  [SEQL*NB*CD];

/* ---------------- generic 32x32 tiled transpose: dst[c][o] = src[o][c] --- */
__global__ void wtr_k(const float* __restrict__ src, float* __restrict__ dst,
                      int O, int Cc, long sStride, long dStride)
{
    src += (size_t)blockIdx.z * sStride;
    dst += (size_t)blockIdx.z * dStride;
    __shared__ float tile[32][33];
    int o0 = blockIdx.x * 32, c0 = blockIdx.y * 32;
    int lx = threadIdx.x & 31, ly = threadIdx.x >> 5;   /* 32 x 8 */
    #pragma unroll
    for (int i = ly; i < 32; i += 8)
        if (o0 + i < O && c0 + lx < Cc)
            tile[i][lx] = src[(size_t)(o0 + i) * Cc + c0 + lx];
    __syncthreads();
    #pragma unroll
    for (int i = ly; i < 32; i += 8)
        if (c0 + i < Cc && o0 + lx < O)
            dst[(size_t)(c0 + i) * O + o0 + lx] = tile[lx][i];
}

/* ---------------- conv weight relayout: [o][c][tap] -> [tap*256+c][o] ---- */
__global__ void wconv_k(const float* __restrict__ mw, float* __restrict__ dst)
{
    int k = blockIdx.x;                 /* 0..2303 */
    int tap = k >> 8, c = k & 255;
    int o = threadIdx.x;
    dst[(size_t)k * CD + o] = mw[((size_t)o * 776 + c) * 9 + tap];
}

/* ---------------- hn tap sums: hnTap[n][o][tap] = sum_c hn[n][c]*W -------- */
__global__ void hntap_k(const float* __restrict__ hn, const float* __restrict__ mw,
                        float* __restrict__ out)
{
    int n = blockIdx.x, o = threadIdx.x;
    __shared__ float h[HND];
    for (int i = o; i < HND; i += CD) h[i] = hn[(size_t)n * HND + i];
    __syncthreads();
    float acc[9];
    #pragma unroll
    for (int t = 0; t < 9; t++) acc[t] = 0.f;
    const float* wb = mw + ((size_t)o * 776 + 264) * 9;
    for (int c = 0; c < HND; c++) {
        float hv = h[c];
        #pragma unroll
        for (int t = 0; t < 9; t++) acc[t] += hv * wb[c * 9 + t];
    }
    #pragma unroll
    for (int t = 0; t < 9; t++) out[((size_t)n * CD + o) * 9 + t] = acc[t];
}

/* ---------------- spatial conv (step-invariant, batch-invariant) --------- */
__global__ void sconv_k(const float* __restrict__ mw, float* __restrict__ out)
{
    int p = blockIdx.x, o = threadIdx.x;
    int h = p >> 5, w = p & 31;
    float acc = 0.f;
    const float* wb = mw + ((size_t)o * 776 + 256) * 9;
    for (int ky = 0; ky < 3; ky++) {
        int hh = h + ky - 1; if ((unsigned)hh >= 32u) continue;
        for (int kx = 0; kx < 3; kx++) {
            int ww = w + kx - 1; if ((unsigned)ww >= 32u) continue;
            float xmin = ww * (1.f/16.f) - 1.f, ymin = hh * (1.f/16.f) - 1.f;
            float xmax = (ww + 1) * (1.f/16.f) - 1.f, ymax = (hh + 1) * (1.f/16.f) - 1.f;
            float f[8] = {xmin, ymin, xmax, ymax,
                          0.5f*(xmin+xmax), 0.5f*(ymin+ymax), 1.f/32.f, 1.f/32.f};
            int t = ky * 3 + kx;
            #pragma unroll
            for (int c = 0; c < 8; c++) acc += f[c] * wb[c * 9 + t];
        }
    }
    out[(size_t)p * CD + o] = acc;
}

/* ---------------- base[n][p][o] = sconv + border-case hn taps ------------ */
__global__ void base_k(const float* __restrict__ sc, const float* __restrict__ ht,
                       float* __restrict__ base)
{
    int idx = blockIdx.x;               /* n*1024+p */
    int n = idx >> 10, p = idx & 1023;
    int o = threadIdx.x;
    int h = p >> 5, w = p & 31;
    int ky0 = (h == 0) ? 1 : 0, ky1 = (h == 31) ? 1 : 2;
    int kx0 = (w == 0) ? 1 : 0, kx1 = (w == 31) ? 1 : 2;
    const float* hb = ht + ((size_t)n * CD + o) * 9;
    float acc = sc[(size_t)p * CD + o];
    for (int ky = ky0; ky <= ky1; ky++)
        for (int kx = kx0; kx <= kx1; kx++)
            acc += hb[ky * 3 + kx];
    base[(size_t)idx * CD + o] = acc;
}

/* ---------------- q = relu(emb @ qconv_w^T + qconv_b), all steps --------- */
__global__ void qa_k(const float* __restrict__ emb, const float* __restrict__ qw,
                     const float* __restrict__ qb, float* __restrict__ qa)
{
    int s = blockIdx.x, n = blockIdx.y, tid = threadIdx.x;
    __shared__ float e[304];
    for (int i = tid; i < 300; i += CD) e[i] = emb[((size_t)n * SEQL + s) * 300 + i];
    __syncthreads();
    float acc = qb[tid];
    const float* wr = qw + (size_t)tid * 300;
    for (int i = 0; i < 300; i++) acc += e[i] * wr[i];
    qa[((size_t)s * NB + n) * CD + tid] = fmaxf(acc, 0.f);
}

/* ---------------- qh = q @ Wq^T + bq (P-independent!) -------------------- */
__global__ void qh_k(const float* __restrict__ qa, const float* __restrict__ ipw,
                     const float* __restrict__ ipb, float* __restrict__ qh)
{
    int s = blockIdx.x, n = blockIdx.y, tid = threadIdx.x;
    __shared__ float q[CD];
    q[tid] = qa[((size_t)s * NB + n) * CD + tid];
    __syncthreads();
    float acc = ipb[tid];
    const float* wr = ipw + (size_t)tid * CD;      /* Wq = rows 0..255 */
    #pragma unroll 4
    for (int i = 0; i < CD; i++) acc += q[i] * wr[i];
    qh[((size_t)s * NB + n) * CD + tid] = acc;
}

/* ---------------- workhorse SGEMM: C = A*B + bias + extra, optional relu --
   A: [M][K] row-major (CONV mode: A = featT[n][p][256], K = 9 shifted taps x 256)
   B: [K][Nout] row-major. BM=128 BN=64 BK=16, 128 threads, 8x8 microtile.  */
template<bool CONV>
__global__ void __launch_bounds__(128, 4)
gemm_k(const float* __restrict__ A, const float* __restrict__ B,
       const float* __restrict__ bias, const float* __restrict__ extra,
       float* __restrict__ C, int M, int Nout, int K, int doRelu)
{
    __shared__ float As[16][132];
    __shared__ float Bs[16][68];
    int tid = threadIdx.x;
    int m0 = blockIdx.y * 128;
    int n0 = blockIdx.x * 64;
    int ty = tid >> 3;           /* 0..15 */
    int tx = tid & 7;            /* 0..7  */
    float acc[8][8];
    #pragma unroll
    for (int i = 0; i < 8; i++)
        #pragma unroll
        for (int j = 0; j < 8; j++) acc[i][j] = 0.f;

    for (int k0 = 0; k0 < K; k0 += 16) {
        /* A tile: 128 x 16, stored transposed As[k][m] */
        #pragma unroll
        for (int pass = 0; pass < 4; pass++) {
            int idx = pass * 128 + tid;
            int row = idx >> 2;
            int k4  = (idx & 3) << 2;
            float4 v;
            if (!CONV) {
                v = *reinterpret_cast<const float4*>(A + (size_t)(m0 + row) * K + k0 + k4);
            } else {
                int k = k0 + k4;
                int tap = k >> 8;
                int c = k & 255;
                int dy = tap / 3 - 1, dx = tap % 3 - 1;
                int r = m0 + row;
                int p = r & 1023;
                int h = (p >> 5) + dy, w = (p & 31) + dx;
                if ((unsigned)h < 32u && (unsigned)w < 32u) {
                    int src = (r & ~1023) | (h << 5) | w;
                    v = *reinterpret_cast<const float4*>(A + (size_t)src * 256 + c);
                } else v = make_float4(0.f, 0.f, 0.f, 0.f);
            }
            As[k4 + 0][row] = v.x; As[k4 + 1][row] = v.y;
            As[k4 + 2][row] = v.z; As[k4 + 3][row] = v.w;
        }
        /* B tile: 16 x 64 */
        #pragma unroll
        for (int pass = 0; pass < 2; pass++) {
            int idx = pass * 128 + tid;
            int kk = idx >> 4;
            int nn = (idx & 15) << 2;
            *reinterpret_cast<float4*>(&Bs[kk][nn]) =
                *reinterpret_cast<const float4*>(B + (size_t)(k0 + kk) * Nout + n0 + nn);
        }
        __syncthreads();
        #pragma unroll
        for (int kk = 0; kk < 16; kk++) {
            float a[8], b[8];
            *reinterpret_cast<float4*>(&a[0]) = *reinterpret_cast<float4*>(&As[kk][ty * 8]);
            *reinterpret_cast<float4*>(&a[4]) = *reinterpret_cast<float4*>(&As[kk][ty * 8 + 4]);
            *reinterpret_cast<float4*>(&b[0]) = *reinterpret_cast<float4*>(&Bs[kk][tx * 8]);
            *reinterpret_cast<float4*>(&b[4]) = *reinterpret_cast<float4*>(&Bs[kk][tx * 8 + 4]);
            #pragma unroll
            for (int i = 0; i < 8; i++)
                #pragma unroll
                for (int j = 0; j < 8; j++) acc[i][j] += a[i] * b[j];
        }
        __syncthreads();
    }
    #pragma unroll
    for (int i = 0; i < 8; i++) {
        int r = m0 + ty * 8 + i;
        #pragma unroll
        for (int j = 0; j < 8; j += 4) {
            int nc = n0 + tx * 8 + j;
            float4 v = make_float4(acc[i][j], acc[i][j+1], acc[i][j+2], acc[i][j+3]);
            if (bias) {
                v.x += bias[nc]; v.y += bias[nc+1]; v.z += bias[nc+2]; v.w += bias[nc+3];
            }
            if (extra) {
                float4 e = *reinterpret_cast<const float4*>(extra + (size_t)r * Nout + nc);
                v.x += e.x; v.y += e.y; v.z += e.z; v.w += e.w;
            }
            if (doRelu) {
                v.x = fmaxf(v.x, 0.f); v.y = fmaxf(v.y, 0.f);
                v.z = fmaxf(v.z, 0.f); v.w = fmaxf(v.w, 0.f);
            }
            *reinterpret_cast<float4*>(C + (size_t)r * Nout + nc) = v;
        }
    }
}

/* ---------------- layernorm over 256 ch; optional conditional commit ----- */
__global__ void ln_k(const float* __restrict__ X, const float* __restrict__ g,
                     const float* __restrict__ b, float* __restrict__ Y,
                     const int* __restrict__ words, int step)
{
    int row = blockIdx.x;
    int tid = threadIdx.x;                  /* 256 */
    float x = X[(size_t)row * CD + tid];
    float s = x, ss = x * x;
    #pragma unroll
    for (int off = 16; off; off >>= 1) {
        s  += __shfl_xor_sync(0xffffffffu, s, off);
        ss += __shfl_xor_sync(0xffffffffu, ss, off);
    }
    __shared__ float sh[16];
    int w = tid >> 5, l = tid & 31;
    if (l == 0) { sh[w] = s; sh[8 + w] = ss; }
    __syncthreads();
    float tot = 0.f, tot2 = 0.f;
    #pragma unroll
    for (int i = 0; i < 8; i++) { tot += sh[i]; tot2 += sh[8 + i]; }
    float mean = tot * (1.f / 256.f);
    float var = tot2 * (1.f / 256.f) - mean * mean;
    float y = (x - mean) * rsqrtf(var + 1e-5f) * g[tid] + b[tid];
    if (words && words[step] == 0) return;  /* inactive step: keep old state */
    Y[(size_t)row * CD + tid] = y;
}

/* ---------------- attention: per (p, head), 16x16 over batch ------------- */
__global__ void attn_k(const float* __restrict__ kv, const float* __restrict__ qh,
                       float* __restrict__ obuf, int step)
{
    int p = blockIdx.x, hd = blockIdx.y;
    int tid = threadIdx.x;                  /* 256 */
    __shared__ float qs[16][128], ks[16][128], vs[16][128], at[16][17];
    const float* qbase = qh + (size_t)step * NB * CD + hd * 128;
    for (int i = tid; i < 16 * 128; i += 256) {
        int l = i >> 7, d = i & 127;
        qs[l][d] = qbase[(size_t)l * CD + d];
        ks[l][d] = kv[(((size_t)l << 10) + p) * 512 + hd * 128 + d];
        vs[l][d] = kv[(((size_t)l << 10) + p) * 512 + 256 + hd * 128 + d];
    }
    __syncthreads();
    {
        int l = tid >> 4, m = tid & 15;
        float s = 0.f;
        #pragma unroll 8
        for (int d = 0; d < 128; d++) s += qs[l][d] * ks[m][d];
        s *= 0.08838834764831845f;          /* 1/sqrt(128) */
        float mx = s;
        #pragma unroll
        for (int off = 8; off; off >>= 1) mx = fmaxf(mx, __shfl_xor_sync(0xffffffffu, mx, off));
        float e = expf(s - mx);
        float sum = e;
        #pragma unroll
        for (int off = 8; off; off >>= 1) sum += __shfl_xor_sync(0xffffffffu, sum, off);
        at[l][m] = e / sum;
    }
    __syncthreads();
    {
        int l = tid >> 4;
        int d0 = (tid & 15) * 8;
        float acc[8];
        #pragma unroll
        for (int j = 0; j < 8; j++) acc[j] = 0.f;
        #pragma unroll
        for (int m = 0; m < 16; m++) {
            float a = at[l][m];
            #pragma unroll
            for (int j = 0; j < 8; j++) acc[j] += a * vs[m][d0 + j];
        }
        float* o = obuf + (((size_t)l << 10) + p) * CD + hd * 128 + d0;
        #pragma unroll
        for (int j = 0; j < 8; j++) o[j] = acc[j];
    }
}

/* ======================================================================== */
extern "C" void kernel_launch(void* const* d_in, const int* in_sizes, int n_in,
                              void* d_out, int out_size)
{
    const float* hn      = (const float*)d_in[1];
    const float* feature = (const float*)d_in[2];
    const float* emb     = (const float*)d_in[3];
    const int*   words   = (const int*)  d_in[4];
    const float* qw      = (const float*)d_in[5];
    const float* qb      = (const float*)d_in[6];
    const float* mw      = (const float*)d_in[7];
    const float* mg      = (const float*)d_in[8];
    const float* mb      = (const float*)d_in[9];
    const float* ipw     = (const float*)d_in[10];
    const float* ipb     = (const float*)d_in[11];
    const float* opw     = (const float*)d_in[12];
    const float* opb     = (const float*)d_in[13];
    const float* ng      = (const float*)d_in[14];
    const float* nbv     = (const float*)d_in[15];
    const float* w1      = (const float*)d_in[16];
    const float* b1      = (const float*)d_in[17];
    const float* w2      = (const float*)d_in[18];
    const float* b2      = (const float*)d_in[19];
    const float* nfg     = (const float*)d_in[20];
    const float* nfb     = (const float*)d_in[21];

    float *featT, *base, *t, *fea, *s1, *s2, *kvb;
    float *wConvT, *wkvT, *woT, *w1T, *w2T, *hnTap, *sconv, *qhall, *qall;
    cudaGetSymbolAddress((void**)&featT, g_featT);
    cudaGetSymbolAddress((void**)&base,  g_base);
    cudaGetSymbolAddress((void**)&t,     g_t);
    cudaGetSymbolAddress((void**)&fea,   g_fea);
    cudaGetSymbolAddress((void**)&s1,    g_s1);
    cudaGetSymbolAddress((void**)&s2,    g_s2);
    cudaGetSymbolAddress((void**)&kvb,   g_kv);
    cudaGetSymbolAddress((void**)&wConvT,g_wConvT);
    cudaGetSymbolAddress((void**)&wkvT,  g_wkvT);
    cudaGetSymbolAddress((void**)&woT,   g_woT);
    cudaGetSymbolAddress((void**)&w1T,   g_w1T);
    cudaGetSymbolAddress((void**)&w2T,   g_w2T);
    cudaGetSymbolAddress((void**)&hnTap, g_hnTap);
    cudaGetSymbolAddress((void**)&sconv, g_sconv);
    cudaGetSymbolAddress((void**)&qhall, g_qhall);
    cudaGetSymbolAddress((void**)&qall,  g_qall);

    /* ---- precompute ---- */
    /* featT[n][p][c] = feature[n][c][p] */
    wtr_k<<<dim3(8, 32, NB), 256>>>(feature, featT, 256, 1024,
                                    (long)256 * 1024, (long)1024 * 256);
    wconv_k<<<KCONV, 256>>>(mw, wConvT);
    /* wkvT[c][o2] = in_proj_w[256+o2][c] */
    wtr_k<<<dim3(16, 8, 1), 256>>>(ipw + 256 * 256, wkvT, 512, 256, 0, 0);
    wtr_k<<<dim3(8, 8, 1), 256>>>(opw, woT, 256, 256, 0, 0);
    wtr_k<<<dim3(8, 8, 1), 256>>>(w1, w1T, 256, 256, 0, 0);
    wtr_k<<<dim3(8, 8, 1), 256>>>(w2, w2T, 256, 256, 0, 0);
    hntap_k<<<NB, 256>>>(hn, mw, hnTap);
    sconv_k<<<PTOT, 256>>>(mw, sconv);
    base_k<<<MROWS, 256>>>(sconv, hnTap, base);
    qa_k<<<dim3(SEQL, NB), 256>>>(emb, qw, qb, qall);
    qh_k<<<dim3(SEQL, NB), 256>>>(qall, ipw, ipb, qhall);

    /* ---- 20 recurrent steps ---- */
    for (int s = 0; s < SEQL; s++) {
        /* conv(feat) + base, relu  -> s1 */
        gemm_k<true><<<dim3(4, 128), 128>>>(featT, wConvT, nullptr, base,
                                            s1, MROWS, 256, KCONV, 1);
        ln_k<<<MROWS, 256>>>(s1, mg, mb, t, nullptr, 0);
        /* kh|vv = t @ [Wk;Wv]^T + b  -> kv */
        gemm_k<false><<<dim3(8, 128), 128>>>(t, wkvT, ipb + 256, nullptr,
                                             kvb, MROWS, 512, 256, 0);
        attn_k<<<dim3(PTOT, 2), 256>>>(kvb, qhall, s2, s);
        /* fea_raw = t + o @ Wo^T + bo -> s1 */
        gemm_k<false><<<dim3(4, 128), 128>>>(s2, woT, opb, t,
                                             s1, MROWS, 256, 256, 0);
        ln_k<<<MROWS, 256>>>(s1, ng, nbv, fea, nullptr, 0);
        /* h1 = relu(fea @ W1^T + b1) -> s2 */
        gemm_k<false><<<dim3(4, 128), 128>>>(fea, w1T, b1, nullptr,
                                             s2, MROWS, 256, 256, 1);
        /* f2_raw = fea + h1 @ W2^T + b2 -> s1 */
        gemm_k<false><<<dim3(4, 128), 128>>>(s2, w2T, b2, fea,
                                             s1, MROWS, 256, 256, 0);
        /* LN + conditional commit into state */
        ln_k<<<MROWS, 256>>>(s1, nfg, nfb, featT, words, s);
    }

    /* d_out[n][c][p] = featT[n][p][c] */
    wtr_k<<<dim3(32, 8, NB), 256>>>(featT, (float*)d_out, 1024, 256,
                                    (long)1024 * 256, (long)256 * 1024);
    (void)in_sizes; (void)n_in; (void)out_size;
}

// round 4
// speedup vs baseline: 1.9453x; 1.9453x over previous
#include <cuda_runtime.h>
#include <math.h>
#include <stdint.h>

#define NB    16
#define PTOT  1024
#define CD    256
#define HND   512
#define SEQL  20
#define MROWS (NB*PTOT)        /* 16384 */
#define KCONV 2304             /* 9 taps * 256 ch */

/* ---------------- scratch (device globals; no allocation allowed) -------- */
__device__ float g_featT [MROWS*CD];      /* state, [n][p][c] */
__device__ float g_base  [MROWS*CD];      /* precomputed spatial+hn conv contribution */
__device__ float g_t     [MROWS*CD];
__device__ float g_fea   [MROWS*CD];
__device__ float g_s1    [MROWS*CD];
__device__ float g_s2    [MROWS*CD];
__device__ float g_kv    [MROWS*2*CD];    /* kh | vv */
__device__ float g_wConvT[KCONV*CD];      /* [tap*256+c][o] */
__device__ float g_wkvT  [CD*2*CD];
__device__ float g_woT   [CD*CD];
__device__ float g_w1T   [CD*CD];
__device__ float g_w2T   [CD*CD];
__device__ float g_hnTap [NB*CD*9];
__device__ float g_sconv [PTOT*CD];
__device__ float g_qhall [SEQL*NB*CD];
__device__ float g_qall  [SEQL*NB*CD];

/* ---------------- tf32 round helper -------------------------------------- */
__device__ __forceinline__ float ftf32(float x)
{
    uint32_t u;
    asm("cvt.rna.tf32.f32 %0, %1;" : "=r"(u) : "f"(x));
    return __uint_as_float(u);
}

/* ---------------- generic 32x32 tiled transpose: dst[c][o] = src[o][c] --- */
__global__ void wtr_k(const float* __restrict__ src, float* __restrict__ dst,
                      int O, int Cc, long sStride, long dStride)
{
    src += (size_t)blockIdx.z * sStride;
    dst += (size_t)blockIdx.z * dStride;
    __shared__ float tile[32][33];
    int o0 = blockIdx.x * 32, c0 = blockIdx.y * 32;
    int lx = threadIdx.x & 31, ly = threadIdx.x >> 5;   /* 32 x 8 */
    #pragma unroll
    for (int i = ly; i < 32; i += 8)
        if (o0 + i < O && c0 + lx < Cc)
            tile[i][lx] = src[(size_t)(o0 + i) * Cc + c0 + lx];
    __syncthreads();
    #pragma unroll
    for (int i = ly; i < 32; i += 8)
        if (c0 + i < Cc && o0 + lx < O)
            dst[(size_t)(c0 + i) * O + o0 + lx] = tile[lx][i];
}

/* ---------------- conv weight relayout: [o][c][tap] -> [tap*256+c][o] ---- */
__global__ void wconv_k(const float* __restrict__ mw, float* __restrict__ dst)
{
    int k = blockIdx.x;
    int tap = k >> 8, c = k & 255;
    int o = threadIdx.x;
    dst[(size_t)k * CD + o] = mw[((size_t)o * 776 + c) * 9 + tap];
}

/* ---------------- hn tap sums -------------------------------------------- */
__global__ void hntap_k(const float* __restrict__ hn, const float* __restrict__ mw,
                        float* __restrict__ out)
{
    int n = blockIdx.x, o = threadIdx.x;
    __shared__ float h[HND];
    for (int i = o; i < HND; i += CD) h[i] = hn[(size_t)n * HND + i];
    __syncthreads();
    float acc[9];
    #pragma unroll
    for (int t = 0; t < 9; t++) acc[t] = 0.f;
    const float* wb = mw + ((size_t)o * 776 + 264) * 9;
    for (int c = 0; c < HND; c++) {
        float hv = h[c];
        #pragma unroll
        for (int t = 0; t < 9; t++) acc[t] += hv * wb[c * 9 + t];
    }
    #pragma unroll
    for (int t = 0; t < 9; t++) out[((size_t)n * CD + o) * 9 + t] = acc[t];
}

/* ---------------- spatial conv (invariant) ------------------------------- */
__global__ void sconv_k(const float* __restrict__ mw, float* __restrict__ out)
{
    int p = blockIdx.x, o = threadIdx.x;
    int h = p >> 5, w = p & 31;
    float acc = 0.f;
    const float* wb = mw + ((size_t)o * 776 + 256) * 9;
    for (int ky = 0; ky < 3; ky++) {
        int hh = h + ky - 1; if ((unsigned)hh >= 32u) continue;
        for (int kx = 0; kx < 3; kx++) {
            int ww = w + kx - 1; if ((unsigned)ww >= 32u) continue;
            float xmin = ww * (1.f/16.f) - 1.f, ymin = hh * (1.f/16.f) - 1.f;
            float xmax = (ww + 1) * (1.f/16.f) - 1.f, ymax = (hh + 1) * (1.f/16.f) - 1.f;
            float f[8] = {xmin, ymin, xmax, ymax,
                          0.5f*(xmin+xmax), 0.5f*(ymin+ymax), 1.f/32.f, 1.f/32.f};
            int t = ky * 3 + kx;
            #pragma unroll
            for (int c = 0; c < 8; c++) acc += f[c] * wb[c * 9 + t];
        }
    }
    out[(size_t)p * CD + o] = acc;
}

/* ---------------- base[n][p][o] = sconv + border-case hn taps ------------ */
__global__ void base_k(const float* __restrict__ sc, const float* __restrict__ ht,
                       float* __restrict__ base)
{
    int idx = blockIdx.x;
    int n = idx >> 10, p = idx & 1023;
    int o = threadIdx.x;
    int h = p >> 5, w = p & 31;
    int ky0 = (h == 0) ? 1 : 0, ky1 = (h == 31) ? 1 : 2;
    int kx0 = (w == 0) ? 1 : 0, kx1 = (w == 31) ? 1 : 2;
    const float* hb = ht + ((size_t)n * CD + o) * 9;
    float acc = sc[(size_t)p * CD + o];
    for (int ky = ky0; ky <= ky1; ky++)
        for (int kx = kx0; kx <= kx1; kx++)
            acc += hb[ky * 3 + kx];
    base[(size_t)idx * CD + o] = acc;
}

/* ---------------- q = relu(emb @ qconv_w^T + qconv_b), all steps --------- */
__global__ void qa_k(const float* __restrict__ emb, const float* __restrict__ qw,
                     const float* __restrict__ qb, float* __restrict__ qa)
{
    int s = blockIdx.x, n = blockIdx.y, tid = threadIdx.x;
    __shared__ float e[304];
    for (int i = tid; i < 300; i += CD) e[i] = emb[((size_t)n * SEQL + s) * 300 + i];
    __syncthreads();
    float acc = qb[tid];
    const float* wr = qw + (size_t)tid * 300;
    for (int i = 0; i < 300; i++) acc += e[i] * wr[i];
    qa[((size_t)s * NB + n) * CD + tid] = fmaxf(acc, 0.f);
}

/* ---------------- qh = q @ Wq^T + bq ------------------------------------- */
__global__ void qh_k(const float* __restrict__ qa, const float* __restrict__ ipw,
                     const float* __restrict__ ipb, float* __restrict__ qh)
{
    int s = blockIdx.x, n = blockIdx.y, tid = threadIdx.x;
    __shared__ float q[CD];
    q[tid] = qa[((size_t)s * NB + n) * CD + tid];
    __syncthreads();
    float acc = ipb[tid];
    const float* wr = ipw + (size_t)tid * CD;
    #pragma unroll 4
    for (int i = 0; i < CD; i++) acc += q[i] * wr[i];
    qh[((size_t)s * NB + n) * CD + tid] = acc;
}

/* =================== tf32 tensor-core GEMM ================================
   C = A*B (+bias)(+extra)(relu).  A:[M][K] rm (CONV: implicit 3x3 gather),
   B:[K][N] rm.  CTA tile 128x64, BK=32, 256 thr = 8 warps (4M x 2N),
   warp tile 32x32 = 2x4 m16n8k8 frags, fp32 accum.                        */
#define MMA_TF32(d, a, b) \
    asm volatile("mma.sync.aligned.m16n8k8.row.col.f32.tf32.tf32.f32 " \
                 "{%0,%1,%2,%3}, {%4,%5,%6,%7}, {%8,%9}, {%0,%1,%2,%3};" \
                 : "+f"(d[0]), "+f"(d[1]), "+f"(d[2]), "+f"(d[3]) \
                 : "r"(a[0]), "r"(a[1]), "r"(a[2]), "r"(a[3]), \
                   "r"(b[0]), "r"(b[1]))

template<bool CONV>
__global__ void __launch_bounds__(256, 2)
gemm_k(const float* __restrict__ A, const float* __restrict__ B,
       const float* __restrict__ bias, const float* __restrict__ extra,
       float* __restrict__ C, int M, int Nout, int K, int doRelu)
{
    __shared__ float As[128][36];   /* [m][k], stride 36: conflict-free frags */
    __shared__ float Bs[32][72];    /* [k][n], stride 72: conflict-free frags */
    int tid  = threadIdx.x;
    int m0   = blockIdx.y * 128;
    int n0   = blockIdx.x * 64;
    int warp = tid >> 5;
    int lane = tid & 31;
    int wM = warp & 3;              /* 0..3 -> M offset 32*wM */
    int wN = warp >> 2;             /* 0..1 -> N offset 32*wN */
    int gid = lane >> 2;            /* 0..7 */
    int tig = lane & 3;             /* 0..3 */

    float acc[2][4][4];
    #pragma unroll
    for (int i = 0; i < 2; i++)
        #pragma unroll
        for (int j = 0; j < 4; j++)
            #pragma unroll
            for (int r = 0; r < 4; r++) acc[i][j][r] = 0.f;

    for (int k0 = 0; k0 < K; k0 += 32) {
        /* A tile 128x32: 1024 float4, 4 per thread, tf32-rounded into SMEM */
        #pragma unroll
        for (int pass = 0; pass < 4; pass++) {
            int idx = pass * 256 + tid;
            int row = idx >> 3;
            int k4  = (idx & 7) << 2;
            float4 v;
            if (!CONV) {
                v = *reinterpret_cast<const float4*>(A + (size_t)(m0 + row) * K + k0 + k4);
            } else {
                int k = k0 + k4;
                int tap = k >> 8;
                int c = k & 255;
                int dy = tap / 3 - 1, dx = tap % 3 - 1;
                int r = m0 + row;
                int p = r & 1023;
                int h = (p >> 5) + dy, w = (p & 31) + dx;
                if ((unsigned)h < 32u && (unsigned)w < 32u) {
                    int src = (r & ~1023) | (h << 5) | w;
                    v = *reinterpret_cast<const float4*>(A + (size_t)src * 256 + c);
                } else v = make_float4(0.f, 0.f, 0.f, 0.f);
            }
            float* dstp = &As[row][k4];
            dstp[0] = ftf32(v.x); dstp[1] = ftf32(v.y);
            dstp[2] = ftf32(v.z); dstp[3] = ftf32(v.w);
        }
        /* B tile 32x64: 512 float4, 2 per thread */
        #pragma unroll
        for (int pass = 0; pass < 2; pass++) {
            int idx = pass * 256 + tid;
            int kk = idx >> 4;
            int nn = (idx & 15) << 2;
            float4 v = *reinterpret_cast<const float4*>(B + (size_t)(k0 + kk) * Nout + n0 + nn);
            float* dstp = &Bs[kk][nn];
            dstp[0] = ftf32(v.x); dstp[1] = ftf32(v.y);
            dstp[2] = ftf32(v.z); dstp[3] = ftf32(v.w);
        }
        __syncthreads();

        #pragma unroll
        for (int ks = 0; ks < 4; ks++) {
            int kb = ks << 3;
            uint32_t a[2][4], b[4][2];
            #pragma unroll
            for (int mf = 0; mf < 2; mf++) {
                int row = wM * 32 + mf * 16 + gid;
                a[mf][0] = __float_as_uint(As[row    ][kb + tig    ]);
                a[mf][1] = __float_as_uint(As[row + 8][kb + tig    ]);
                a[mf][2] = __float_as_uint(As[row    ][kb + tig + 4]);
                a[mf][3] = __float_as_uint(As[row + 8][kb + tig + 4]);
            }
            #pragma unroll
            for (int nf = 0; nf < 4; nf++) {
                int col = wN * 32 + nf * 8 + gid;
                b[nf][0] = __float_as_uint(Bs[kb + tig    ][col]);
                b[nf][1] = __float_as_uint(Bs[kb + tig + 4][col]);
            }
            #pragma unroll
            for (int mf = 0; mf < 2; mf++)
                #pragma unroll
                for (int nf = 0; nf < 4; nf++)
                    MMA_TF32(acc[mf][nf], a[mf], b[nf]);
        }
        __syncthreads();
    }

    /* epilogue: c0,c1 -> (row, col..col+1), c2,c3 -> (row+8, ...) */
    #pragma unroll
    for (int mf = 0; mf < 2; mf++) {
        int row = m0 + wM * 32 + mf * 16 + gid;
        #pragma unroll
        for (int nf = 0; nf < 4; nf++) {
            int col = n0 + wN * 32 + nf * 8 + 2 * tig;
            float2 v0 = make_float2(acc[mf][nf][0], acc[mf][nf][1]);
            float2 v1 = make_float2(acc[mf][nf][2], acc[mf][nf][3]);
            if (bias) {
                float2 bb = *reinterpret_cast<const float2*>(bias + col);
                v0.x += bb.x; v0.y += bb.y; v1.x += bb.x; v1.y += bb.y;
            }
            if (extra) {
                float2 e0 = *reinterpret_cast<const float2*>(extra + (size_t)row * Nout + col);
                float2 e1 = *reinterpret_cast<const float2*>(extra + (size_t)(row + 8) * Nout + col);
                v0.x += e0.x; v0.y += e0.y; v1.x += e1.x; v1.y += e1.y;
            }
            if (doRelu) {
                v0.x = fmaxf(v0.x, 0.f); v0.y = fmaxf(v0.y, 0.f);
                v1.x = fmaxf(v1.x, 0.f); v1.y = fmaxf(v1.y, 0.f);
            }
            *reinterpret_cast<float2*>(C + (size_t)row * Nout + col) = v0;
            *reinterpret_cast<float2*>(C + (size_t)(row + 8) * Nout + col) = v1;
        }
    }
}

/* ---------------- layernorm over 256 ch; optional conditional commit ----- */
__global__ void ln_k(const float* __restrict__ X, const float* __restrict__ g,
                     const float* __restrict__ b, float* __restrict__ Y,
                     const int* __restrict__ words, int step)
{
    int row = blockIdx.x;
    int tid = threadIdx.x;
    float x = X[(size_t)row * CD + tid];
    float s = x, ss = x * x;
    #pragma unroll
    for (int off = 16; off; off >>= 1) {
        s  += __shfl_xor_sync(0xffffffffu, s, off);
        ss += __shfl_xor_sync(0xffffffffu, ss, off);
    }
    __shared__ float sh[16];
    int w = tid >> 5, l = tid & 31;
    if (l == 0) { sh[w] = s; sh[8 + w] = ss; }
    __syncthreads();
    float tot = 0.f, tot2 = 0.f;
    #pragma unroll
    for (int i = 0; i < 8; i++) { tot += sh[i]; tot2 += sh[8 + i]; }
    float mean = tot * (1.f / 256.f);
    float var = tot2 * (1.f / 256.f) - mean * mean;
    float y = (x - mean) * rsqrtf(var + 1e-5f) * g[tid] + b[tid];
    if (words && words[step] == 0) return;
    Y[(size_t)row * CD + tid] = y;
}

/* ---------------- attention: per (p, head), 16x16 over batch ------------- */
__global__ void attn_k(const float* __restrict__ kv, const float* __restrict__ qh,
                       float* __restrict__ obuf, int step)
{
    int p = blockIdx.x, hd = blockIdx.y;
    int tid = threadIdx.x;
    __shared__ float qs[16][128], ks[16][128], vs[16][128], at[16][17];
    const float* qbase = qh + (size_t)step * NB * CD + hd * 128;
    for (int i = tid; i < 16 * 128; i += 256) {
        int l = i >> 7, d = i & 127;
        qs[l][d] = qbase[(size_t)l * CD + d];
        ks[l][d] = kv[(((size_t)l << 10) + p) * 512 + hd * 128 + d];
        vs[l][d] = kv[(((size_t)l << 10) + p) * 512 + 256 + hd * 128 + d];
    }
    __syncthreads();
    {
        int l = tid >> 4, m = tid & 15;
        float s = 0.f;
        #pragma unroll 8
        for (int d = 0; d < 128; d++) s += qs[l][d] * ks[m][d];
        s *= 0.08838834764831845f;
        float mx = s;
        #pragma unroll
        for (int off = 8; off; off >>= 1) mx = fmaxf(mx, __shfl_xor_sync(0xffffffffu, mx, off));
        float e = expf(s - mx);
        float sum = e;
        #pragma unroll
        for (int off = 8; off; off >>= 1) sum += __shfl_xor_sync(0xffffffffu, sum, off);
        at[l][m] = e / sum;
    }
    __syncthreads();
    {
        int l = tid >> 4;
        int d0 = (tid & 15) * 8;
        float acc[8];
        #pragma unroll
        for (int j = 0; j < 8; j++) acc[j] = 0.f;
        #pragma unroll
        for (int m = 0; m < 16; m++) {
            float a = at[l][m];
            #pragma unroll
            for (int j = 0; j < 8; j++) acc[j] += a * vs[m][d0 + j];
        }
        float* o = obuf + (((size_t)l << 10) + p) * CD + hd * 128 + d0;
        #pragma unroll
        for (int j = 0; j < 8; j++) o[j] = acc[j];
    }
}

/* ======================================================================== */
extern "C" void kernel_launch(void* const* d_in, const int* in_sizes, int n_in,
                              void* d_out, int out_size)
{
    const float* hn      = (const float*)d_in[1];
    const float* feature = (const float*)d_in[2];
    const float* emb     = (const float*)d_in[3];
    const int*   words   = (const int*)  d_in[4];
    const float* qw      = (const float*)d_in[5];
    const float* qb      = (const float*)d_in[6];
    const float* mw      = (const float*)d_in[7];
    const float* mg      = (const float*)d_in[8];
    const float* mb      = (const float*)d_in[9];
    const float* ipw     = (const float*)d_in[10];
    const float* ipb     = (const float*)d_in[11];
    const float* opw     = (const float*)d_in[12];
    const float* opb     = (const float*)d_in[13];
    const float* ng      = (const float*)d_in[14];
    const float* nbv     = (const float*)d_in[15];
    const float* w1      = (const float*)d_in[16];
    const float* b1      = (const float*)d_in[17];
    const float* w2      = (const float*)d_in[18];
    const float* b2      = (const float*)d_in[19];
    const float* nfg     = (const float*)d_in[20];
    const float* nfb     = (const float*)d_in[21];

    float *featT, *base, *t, *fea, *s1, *s2, *kvb;
    float *wConvT, *wkvT, *woT, *w1T, *w2T, *hnTap, *sconv, *qhall, *qall;
    cudaGetSymbolAddress((void**)&featT, g_featT);
    cudaGetSymbolAddress((void**)&base,  g_base);
    cudaGetSymbolAddress((void**)&t,     g_t);
    cudaGetSymbolAddress((void**)&fea,   g_fea);
    cudaGetSymbolAddress((void**)&s1,    g_s1);
    cudaGetSymbolAddress((void**)&s2,    g_s2);
    cudaGetSymbolAddress((void**)&kvb,   g_kv);
    cudaGetSymbolAddress((void**)&wConvT,g_wConvT);
    cudaGetSymbolAddress((void**)&wkvT,  g_wkvT);
    cudaGetSymbolAddress((void**)&woT,   g_woT);
    cudaGetSymbolAddress((void**)&w1T,   g_w1T);
    cudaGetSymbolAddress((void**)&w2T,   g_w2T);
    cudaGetSymbolAddress((void**)&hnTap, g_hnTap);
    cudaGetSymbolAddress((void**)&sconv, g_sconv);
    cudaGetSymbolAddress((void**)&qhall, g_qhall);
    cudaGetSymbolAddress((void**)&qall,  g_qall);

    /* ---- precompute ---- */
    wtr_k<<<dim3(8, 32, NB), 256>>>(feature, featT, 256, 1024,
                                    (long)256 * 1024, (long)1024 * 256);
    wconv_k<<<KCONV, 256>>>(mw, wConvT);
    wtr_k<<<dim3(16, 8, 1), 256>>>(ipw + 256 * 256, wkvT, 512, 256, 0, 0);
    wtr_k<<<dim3(8, 8, 1), 256>>>(opw, woT, 256, 256, 0, 0);
    wtr_k<<<dim3(8, 8, 1), 256>>>(w1, w1T, 256, 256, 0, 0);
    wtr_k<<<dim3(8, 8, 1), 256>>>(w2, w2T, 256, 256, 0, 0);
    hntap_k<<<NB, 256>>>(hn, mw, hnTap);
    sconv_k<<<PTOT, 256>>>(mw, sconv);
    base_k<<<MROWS, 256>>>(sconv, hnTap, base);
    qa_k<<<dim3(SEQL, NB), 256>>>(emb, qw, qb, qall);
    qh_k<<<dim3(SEQL, NB), 256>>>(qall, ipw, ipb, qhall);

    /* ---- 20 recurrent steps ---- */
    for (int s = 0; s < SEQL; s++) {
        gemm_k<true><<<dim3(4, 128), 256>>>(featT, wConvT, nullptr, base,
                                            s1, MROWS, 256, KCONV, 1);
        ln_k<<<MROWS, 256>>>(s1, mg, mb, t, nullptr, 0);
        gemm_k<false><<<dim3(8, 128), 256>>>(t, wkvT, ipb + 256, nullptr,
                                             kvb, MROWS, 512, 256, 0);
        attn_k<<<dim3(PTOT, 2), 256>>>(kvb, qhall, s2, s);
        gemm_k<false><<<dim3(4, 128), 256>>>(s2, woT, opb, t,
                                             s1, MROWS, 256, 256, 0);
        ln_k<<<MROWS, 256>>>(s1, ng, nbv, fea, nullptr, 0);
        gemm_k<false><<<dim3(4, 128), 256>>>(fea, w1T, b1, nullptr,
                                             s2, MROWS, 256, 256, 1);
        gemm_k<false><<<dim3(4, 128), 256>>>(s2, w2T, b2, fea,
                                             s1, MROWS, 256, 256, 0);
        ln_k<<<MROWS, 256>>>(s1, nfg, nfb, featT, words, s);
    }

    wtr_k<<<dim3(32, 8, NB), 256>>>(featT, (float*)d_out, 1024, 256,
                                    (long)1024 * 256, (long)256 * 1024);
    (void)in_sizes; (void)n_in; (void)out_size;
}

// round 7
// speedup vs baseline: 2.1228x; 1.0912x over previous
#include <cuda_runtime.h>
#include <math.h>
#include <stdint.h>

#define NB    16
#define PTOT  1024
#define CD    256
#define HND   512
#define SEQL  20
#define MROWS (NB*PTOT)        /* 16384 */
#define KCONV 2304             /* 9 taps * 256 ch */

/* ---------------- scratch (device globals; no allocation allowed) -------- */
__device__ float g_featT [MROWS*CD];
__device__ float g_base  [MROWS*CD];
__device__ float g_t     [MROWS*CD];
__device__ float g_fea   [MROWS*CD];
__device__ float g_s1    [MROWS*CD];
__device__ float g_s2    [MROWS*CD];
__device__ float g_kv    [MROWS*2*CD];
__device__ float g_wConvT[KCONV*CD];
__device__ float g_wkvT  [CD*2*CD];
__device__ float g_woT   [CD*CD];
__device__ float g_w1T   [CD*CD];
__device__ float g_w2T   [CD*CD];
__device__ float g_hnTap [NB*CD*9];
__device__ float g_sconv [PTOT*CD];
__device__ float g_qhall [SEQL*NB*CD];
__device__ float g_qall  [SEQL*NB*CD];

/* ---------------- tf32 round helper (precompute only) -------------------- */
__device__ __forceinline__ float ftf32(float x)
{
    uint32_t u;
    asm("cvt.rna.tf32.f32 %0, %1;" : "=r"(u) : "f"(x));
    return __uint_as_float(u);
}

/* ---------------- cp.async helpers --------------------------------------- */
__device__ __forceinline__ void cp16(uint32_t d, const void* s, int sz)
{
    asm volatile("cp.async.cg.shared.global [%0], [%1], 16, %2;"
                 :: "r"(d), "l"(s), "r"(sz));
}
#define CP_COMMIT() asm volatile("cp.async.commit_group;")
#define CP_WAIT(n)  asm volatile("cp.async.wait_group %0;" :: "n"(n))

/* ---------------- generic 32x32 tiled transpose: dst[c][o] = src[o][c] --- */
__global__ void wtr_k(const float* __restrict__ src, float* __restrict__ dst,
                      int O, int Cc, long sStride, long dStride, int rnd)
{
    src += (size_t)blockIdx.z * sStride;
    dst += (size_t)blockIdx.z * dStride;
    __shared__ float tile[32][33];
    int o0 = blockIdx.x * 32, c0 = blockIdx.y * 32;
    int lx = threadIdx.x & 31, ly = threadIdx.x >> 5;
    #pragma unroll
    for (int i = ly; i < 32; i += 8)
        if (o0 + i < O && c0 + lx < Cc)
            tile[i][lx] = src[(size_t)(o0 + i) * Cc + c0 + lx];
    __syncthreads();
    #pragma unroll
    for (int i = ly; i < 32; i += 8)
        if (c0 + i < Cc && o0 + lx < O) {
            float v = tile[lx][i];
            dst[(size_t)(c0 + i) * O + o0 + lx] = rnd ? ftf32(v) : v;
        }
}

/* ---------------- conv weight relayout: [o][c][tap] -> [tap*256+c][o] ---- */
__global__ void wconv_k(const float* __restrict__ mw, float* __restrict__ dst)
{
    int k = blockIdx.x;
    int tap = k >> 8, c = k & 255;
    int o = threadIdx.x;
    dst[(size_t)k * CD + o] = ftf32(mw[((size_t)o * 776 + c) * 9 + tap]);
}

/* ---------------- hn tap sums -------------------------------------------- */
__global__ void hntap_k(const float* __restrict__ hn, const float* __restrict__ mw,
                        float* __restrict__ out)
{
    int n = blockIdx.x, o = threadIdx.x;
    __shared__ float h[HND];
    for (int i = o; i < HND; i += CD) h[i] = hn[(size_t)n * HND + i];
    __syncthreads();
    float acc[9];
    #pragma unroll
    for (int t = 0; t < 9; t++) acc[t] = 0.f;
    const float* wb = mw + ((size_t)o * 776 + 264) * 9;
    for (int c = 0; c < HND; c++) {
        float hv = h[c];
        #pragma unroll
        for (int t = 0; t < 9; t++) acc[t] += hv * wb[c * 9 + t];
    }
    #pragma unroll
    for (int t = 0; t < 9; t++) out[((size_t)n * CD + o) * 9 + t] = acc[t];
}

/* ---------------- spatial conv (invariant) ------------------------------- */
__global__ void sconv_k(const float* __restrict__ mw, float* __restrict__ out)
{
    int p = blockIdx.x, o = threadIdx.x;
    int h = p >> 5, w = p & 31;
    float acc = 0.f;
    const float* wb = mw + ((size_t)o * 776 + 256) * 9;
    for (int ky = 0; ky < 3; ky++) {
        int hh = h + ky - 1; if ((unsigned)hh >= 32u) continue;
        for (int kx = 0; kx < 3; kx++) {
            int ww = w + kx - 1; if ((unsigned)ww >= 32u) continue;
            float xmin = ww * (1.f/16.f) - 1.f, ymin = hh * (1.f/16.f) - 1.f;
            float xmax = (ww + 1) * (1.f/16.f) - 1.f, ymax = (hh + 1) * (1.f/16.f) - 1.f;
            float f[8] = {xmin, ymin, xmax, ymax,
                          0.5f*(xmin+xmax), 0.5f*(ymin+ymax), 1.f/32.f, 1.f/32.f};
            int t = ky * 3 + kx;
            #pragma unroll
            for (int c = 0; c < 8; c++) acc += f[c] * wb[c * 9 + t];
        }
    }
    out[(size_t)p * CD + o] = acc;
}

/* ---------------- base[n][p][o] = sconv + border-case hn taps ------------ */
__global__ void base_k(const float* __restrict__ sc, const float* __restrict__ ht,
                       float* __restrict__ base)
{
    int idx = blockIdx.x;
    int n = idx >> 10, p = idx & 1023;
    int o = threadIdx.x;
    int h = p >> 5, w = p & 31;
    int ky0 = (h == 0) ? 1 : 0, ky1 = (h == 31) ? 1 : 2;
    int kx0 = (w == 0) ? 1 : 0, kx1 = (w == 31) ? 1 : 2;
    const float* hb = ht + ((size_t)n * CD + o) * 9;
    float acc = sc[(size_t)p * CD + o];
    for (int ky = ky0; ky <= ky1; ky++)
        for (int kx = kx0; kx <= kx1; kx++)
            acc += hb[ky * 3 + kx];
    base[(size_t)idx * CD + o] = acc;
}

/* ---------------- q = relu(emb @ qconv_w^T + qconv_b), all steps --------- */
__global__ void qa_k(const float* __restrict__ emb, const float* __restrict__ qw,
                     const float* __restrict__ qb, float* __restrict__ qa)
{
    int s = blockIdx.x, n = blockIdx.y, tid = threadIdx.x;
    __shared__ float e[304];
    for (int i = tid; i < 300; i += CD) e[i] = emb[((size_t)n * SEQL + s) * 300 + i];
    __syncthreads();
    float acc = qb[tid];
    const float* wr = qw + (size_t)tid * 300;
    for (int i = 0; i < 300; i++) acc += e[i] * wr[i];
    qa[((size_t)s * NB + n) * CD + tid] = fmaxf(acc, 0.f);
}

/* ---------------- qh = q @ Wq^T + bq ------------------------------------- */
__global__ void qh_k(const float* __restrict__ qa, const float* __restrict__ ipw,
                     const float* __restrict__ ipb, float* __restrict__ qh)
{
    int s = blockIdx.x, n = blockIdx.y, tid = threadIdx.x;
    __shared__ float q[CD];
    q[tid] = qa[((size_t)s * NB + n) * CD + tid];
    __syncthreads();
    float acc = ipb[tid];
    const float* wr = ipw + (size_t)tid * CD;
    #pragma unroll 4
    for (int i = 0; i < CD; i++) acc += q[i] * wr[i];
    qh[((size_t)s * NB + n) * CD + tid] = acc;
}

/* =================== tf32 tensor-core GEMM, double-buffered cp.async =====
   C = A*B (+bias)(+extra)(relu).  A:[M][K] rm (CONV: implicit 3x3 gather),
   B:[K][N] rm.  CTA 128x64, BK=32, 2 stages, 256 thr = 8 warps (4M x 2N),
   warp tile 32x32 = 2x4 m16n8k8 frags, fp32 accum.  fp32->tf32 by HW
   mantissa truncation (weights pre-rounded RNA in precompute).            */
#define AS_STRIDE 36
#define BS_STRIDE 72
#define ASTG (128*AS_STRIDE)
#define STG_ELEMS (ASTG + 32*BS_STRIDE)   /* 6912 floats per stage */
#define GEMM_SMEM (2*STG_ELEMS*4)         /* 55296 bytes */

#define MMA_TF32(d, a, b) \
    asm volatile("mma.sync.aligned.m16n8k8.row.col.f32.tf32.tf32.f32 " \
                 "{%0,%1,%2,%3}, {%4,%5,%6,%7}, {%8,%9}, {%0,%1,%2,%3};" \
                 : "+f"(d[0]), "+f"(d[1]), "+f"(d[2]), "+f"(d[3]) \
                 : "r"(a[0]), "r"(a[1]), "r"(a[2]), "r"(a[3]), \
                   "r"(b[0]), "r"(b[1]))

template<bool CONV>
__device__ __forceinline__ void load_stage(float* stg, const float* A, const float* B,
                                           int m0, int n0, int k0, int K, int Nout, int tid)
{
    /* A tile 128x32 = 1024 x 16B chunks, 4 per thread */
    #pragma unroll
    for (int pass = 0; pass < 4; pass++) {
        int idx = pass * 256 + tid;
        int row = idx >> 3;
        int k4  = (idx & 7) << 2;
        const float* src;
        int sz = 16;
        if (!CONV) {
            src = A + (size_t)(m0 + row) * K + k0 + k4;
        } else {
            int k = k0 + k4;
            int tap = k >> 8;
            int c = k & 255;
            int dy = tap / 3 - 1, dx = tap % 3 - 1;
            int r = m0 + row;
            int p = r & 1023;
            int h = (p >> 5) + dy, w = (p & 31) + dx;
            if ((unsigned)h < 32u && (unsigned)w < 32u) {
                src = A + (size_t)((r & ~1023) | (h << 5) | w) * 256 + c;
            } else { src = A; sz = 0; }    /* zero-fill */
        }
        cp16((uint32_t)__cvta_generic_to_shared(stg + row * AS_STRIDE + k4), src, sz);
    }
    /* B tile 32x64 = 512 x 16B chunks, 2 per thread */
    float* bs = stg + ASTG;
    #pragma unroll
    for (int pass = 0; pass < 2; pass++) {
        int idx = pass * 256 + tid;
        int kk = idx >> 4;
        int nn = (idx & 15) << 2;
        cp16((uint32_t)__cvta_generic_to_shared(bs + kk * BS_STRIDE + nn),
             B + (size_t)(k0 + kk) * Nout + n0 + nn, 16);
    }
    CP_COMMIT();
}

template<bool CONV>
__global__ void __launch_bounds__(256, 2)
gemm_k(const float* __restrict__ A, const float* __restrict__ B,
       const float* __restrict__ bias, const float* __restrict__ extra,
       float* __restrict__ C, int M, int Nout, int K, int doRelu)
{
    extern __shared__ float sm[];
    int tid  = threadIdx.x;
    int m0   = blockIdx.y * 128;
    int n0   = blockIdx.x * 64;
    int warp = tid >> 5;
    int lane = tid & 31;
    int wM = warp & 3;
    int wN = warp >> 2;
    int gid = lane >> 2;
    int tig = lane & 3;

    float acc[2][4][4];
    #pragma unroll
    for (int i = 0; i < 2; i++)
        #pragma unroll
        for (int j = 0; j < 4; j++)
            #pragma unroll
            for (int r = 0; r < 4; r++) acc[i][j][r] = 0.f;

    int nk = K >> 5;
    load_stage<CONV>(sm, A, B, m0, n0, 0, K, Nout, tid);

    for (int ki = 0; ki < nk; ki++) {
        float* As = sm + (ki & 1) * STG_ELEMS;
        float* Bs = As + ASTG;
        if (ki + 1 < nk) {
            load_stage<CONV>(sm + ((ki + 1) & 1) * STG_ELEMS, A, B,
                             m0, n0, (ki + 1) << 5, K, Nout, tid);
            CP_WAIT(1);
        } else {
            CP_WAIT(0);
        }
        __syncthreads();

        #pragma unroll
        for (int ks = 0; ks < 4; ks++) {
            int kb = ks << 3;
            uint32_t a[2][4], b[4][2];
            #pragma unroll
            for (int mf = 0; mf < 2; mf++) {
                int row = wM * 32 + mf * 16 + gid;
                const float* ap = As + row * AS_STRIDE + kb;
                a[mf][0] = __float_as_uint(ap[tig]);
                a[mf][1] = __float_as_uint(ap[8 * AS_STRIDE + tig]);
                a[mf][2] = __float_as_uint(ap[tig + 4]);
                a[mf][3] = __float_as_uint(ap[8 * AS_STRIDE + tig + 4]);
            }
            #pragma unroll
            for (int nf = 0; nf < 4; nf++) {
                int col = wN * 32 + nf * 8 + gid;
                b[nf][0] = __float_as_uint(Bs[(kb + tig) * BS_STRIDE + col]);
                b[nf][1] = __float_as_uint(Bs[(kb + tig + 4) * BS_STRIDE + col]);
            }
            #pragma unroll
            for (int mf = 0; mf < 2; mf++)
                #pragma unroll
                for (int nf = 0; nf < 4; nf++)
                    MMA_TF32(acc[mf][nf], a[mf], b[nf]);
        }
        __syncthreads();
    }

    /* epilogue */
    #pragma unroll
    for (int mf = 0; mf < 2; mf++) {
        int row = m0 + wM * 32 + mf * 16 + gid;
        #pragma unroll
        for (int nf = 0; nf < 4; nf++) {
            int col = n0 + wN * 32 + nf * 8 + 2 * tig;
            float2 v0 = make_float2(acc[mf][nf][0], acc[mf][nf][1]);
            float2 v1 = make_float2(acc[mf][nf][2], acc[mf][nf][3]);
            if (bias) {
                float2 bb = *reinterpret_cast<const float2*>(bias + col);
                v0.x += bb.x; v0.y += bb.y; v1.x += bb.x; v1.y += bb.y;
            }
            if (extra) {
                float2 e0 = *reinterpret_cast<const float2*>(extra + (size_t)row * Nout + col);
                float2 e1 = *reinterpret_cast<const float2*>(extra + (size_t)(row + 8) * Nout + col);
                v0.x += e0.x; v0.y += e0.y; v1.x += e1.x; v1.y += e1.y;
            }
            if (doRelu) {
                v0.x = fmaxf(v0.x, 0.f); v0.y = fmaxf(v0.y, 0.f);
                v1.x = fmaxf(v1.x, 0.f); v1.y = fmaxf(v1.y, 0.f);
            }
            *reinterpret_cast<float2*>(C + (size_t)row * Nout + col) = v0;
            *reinterpret_cast<float2*>(C + (size_t)(row + 8) * Nout + col) = v1;
        }
    }
}

/* ---------------- layernorm over 256 ch; optional conditional commit ----- */
__global__ void ln_k(const float* __restrict__ X, const float* __restrict__ g,
                     const float* __restrict__ b, float* __restrict__ Y,
                     const int* __restrict__ words, int step)
{
    int row = blockIdx.x;
    int tid = threadIdx.x;
    float x = X[(size_t)row * CD + tid];
    float s = x, ss = x * x;
    #pragma unroll
    for (int off = 16; off; off >>= 1) {
        s  += __shfl_xor_sync(0xffffffffu, s, off);
        ss += __shfl_xor_sync(0xffffffffu, ss, off);
    }
    __shared__ float sh[16];
    int w = tid >> 5, l = tid & 31;
    if (l == 0) { sh[w] = s; sh[8 + w] = ss; }
    __syncthreads();
    float tot = 0.f, tot2 = 0.f;
    #pragma unroll
    for (int i = 0; i < 8; i++) { tot += sh[i]; tot2 += sh[8 + i]; }
    float mean = tot * (1.f / 256.f);
    float var = tot2 * (1.f / 256.f) - mean * mean;
    float y = (x - mean) * rsqrtf(var + 1e-5f) * g[tid] + b[tid];
    if (words && words[step] == 0) return;
    Y[(size_t)row * CD + tid] = y;
}

/* ---------------- attention: per (p, head), 16x16 over batch ------------- */
__global__ void attn_k(const float* __restrict__ kv, const float* __restrict__ qh,
                       float* __restrict__ obuf, int step)
{
    int p = blockIdx.x, hd = blockIdx.y;
    int tid = threadIdx.x;
    __shared__ float qs[16][128], ks[16][128], vs[16][128], at[16][17];
    const float* qbase = qh + (size_t)step * NB * CD + hd * 128;
    for (int i = tid; i < 16 * 128; i += 256) {
        int l = i >> 7, d = i & 127;
        qs[l][d] = qbase[(size_t)l * CD + d];
        ks[l][d] = kv[(((size_t)l << 10) + p) * 512 + hd * 128 + d];
        vs[l][d] = kv[(((size_t)l << 10) + p) * 512 + 256 + hd * 128 + d];
    }
    __syncthreads();
    {
        int l = tid >> 4, m = tid & 15;
        float s = 0.f;
        #pragma unroll 8
        for (int d = 0; d < 128; d++) s += qs[l][d] * ks[m][d];
        s *= 0.08838834764831845f;
        float mx = s;
        #pragma unroll
        for (int off = 8; off; off >>= 1) mx = fmaxf(mx, __shfl_xor_sync(0xffffffffu, mx, off));
        float e = expf(s - mx);
        float sum = e;
        #pragma unroll
        for (int off = 8; off; off >>= 1) sum += __shfl_xor_sync(0xffffffffu, sum, off);
        at[l][m] = e / sum;
    }
    __syncthreads();
    {
        int l = tid >> 4;
        int d0 = (tid & 15) * 8;
        float acc[8];
        #pragma unroll
        for (int j = 0; j < 8; j++) acc[j] = 0.f;
        #pragma unroll
        for (int m = 0; m < 16; m++) {
            float a = at[l][m];
            #pragma unroll
            for (int j = 0; j < 8; j++) acc[j] += a * vs[m][d0 + j];
        }
        float* o = obuf + (((size_t)l << 10) + p) * CD + hd * 128 + d0;
        #pragma unroll
        for (int j = 0; j < 8; j++) o[j] = acc[j];
    }
}

/* ======================================================================== */
extern "C" void kernel_launch(void* const* d_in, const int* in_sizes, int n_in,
                              void* d_out, int out_size)
{
    const float* hn      = (const float*)d_in[1];
    const float* feature = (const float*)d_in[2];
    const float* emb     = (const float*)d_in[3];
    const int*   words   = (const int*)  d_in[4];
    const float* qw      = (const float*)d_in[5];
    const float* qb      = (const float*)d_in[6];
    const float* mw      = (const float*)d_in[7];
    const float* mg      = (const float*)d_in[8];
    const float* mb      = (const float*)d_in[9];
    const float* ipw     = (const float*)d_in[10];
    const float* ipb     = (const float*)d_in[11];
    const float* opw     = (const float*)d_in[12];
    const float* opb     = (const float*)d_in[13];
    const float* ng      = (const float*)d_in[14];
    const float* nbv     = (const float*)d_in[15];
    const float* w1      = (const float*)d_in[16];
    const float* b1      = (const float*)d_in[17];
    const float* w2      = (const float*)d_in[18];
    const float* b2      = (const float*)d_in[19];
    const float* nfg     = (const float*)d_in[20];
    const float* nfb     = (const float*)d_in[21];

    float *featT, *base, *t, *fea, *s1, *s2, *kvb;
    float *wConvT, *wkvT, *woT, *w1T, *w2T, *hnTap, *sconv, *qhall, *qall;
    cudaGetSymbolAddress((void**)&featT, g_featT);
    cudaGetSymbolAddress((void**)&base,  g_base);
    cudaGetSymbolAddress((void**)&t,     g_t);
    cudaGetSymbolAddress((void**)&fea,   g_fea);
    cudaGetSymbolAddress((void**)&s1,    g_s1);
    cudaGetSymbolAddress((void**)&s2,    g_s2);
    cudaGetSymbolAddress((void**)&kvb,   g_kv);
    cudaGetSymbolAddress((void**)&wConvT,g_wConvT);
    cudaGetSymbolAddress((void**)&wkvT,  g_wkvT);
    cudaGetSymbolAddress((void**)&woT,   g_woT);
    cudaGetSymbolAddress((void**)&w1T,   g_w1T);
    cudaGetSymbolAddress((void**)&w2T,   g_w2T);
    cudaGetSymbolAddress((void**)&hnTap, g_hnTap);
    cudaGetSymbolAddress((void**)&sconv, g_sconv);
    cudaGetSymbolAddress((void**)&qhall, g_qhall);
    cudaGetSymbolAddress((void**)&qall,  g_qall);

    cudaFuncSetAttribute(gemm_k<true>,  cudaFuncAttributeMaxDynamicSharedMemorySize, GEMM_SMEM);
    cudaFuncSetAttribute(gemm_k<false>, cudaFuncAttributeMaxDynamicSharedMemorySize, GEMM_SMEM);

    /* ---- precompute ---- */
    wtr_k<<<dim3(8, 32, NB), 256>>>(feature, featT, 256, 1024,
                                    (long)256 * 1024, (long)1024 * 256, 0);
    wconv_k<<<KCONV, 256>>>(mw, wConvT);
    wtr_k<<<dim3(16, 8, 1), 256>>>(ipw + 256 * 256, wkvT, 512, 256, 0, 0, 1);
    wtr_k<<<dim3(8, 8, 1), 256>>>(opw, woT, 256, 256, 0, 0, 1);
    wtr_k<<<dim3(8, 8, 1), 256>>>(w1, w1T, 256, 256, 0, 0, 1);
    wtr_k<<<dim3(8, 8, 1), 256>>>(w2, w2T, 256, 256, 0, 0, 1);
    hntap_k<<<NB, 256>>>(hn, mw, hnTap);
    sconv_k<<<PTOT, 256>>>(mw, sconv);
    base_k<<<MROWS, 256>>>(sconv, hnTap, base);
    qa_k<<<dim3(SEQL, NB), 256>>>(emb, qw, qb, qall);
    qh_k<<<dim3(SEQL, NB), 256>>>(qall, ipw, ipb, qhall);

    /* ---- 20 recurrent steps ---- */
    for (int s = 0; s < SEQL; s++) {
        gemm_k<true><<<dim3(4, 128), 256, GEMM_SMEM>>>(featT, wConvT, nullptr, base,
                                                       s1, MROWS, 256, KCONV, 1);
        ln_k<<<MROWS, 256>>>(s1, mg, mb, t, nullptr, 0);
        gemm_k<false><<<dim3(8, 128), 256, GEMM_SMEM>>>(t, wkvT, ipb + 256, nullptr,
                                                        kvb, MROWS, 512, 256, 0);
        attn_k<<<dim3(PTOT, 2), 256>>>(kvb, qhall, s2, s);
        gemm_k<false><<<dim3(4, 128), 256, GEMM_SMEM>>>(s2, woT, opb, t,
                                                        s1, MROWS, 256, 256, 0);
        ln_k<<<MROWS, 256>>>(s1, ng, nbv, fea, nullptr, 0);
        gemm_k<false><<<dim3(4, 128), 256, GEMM_SMEM>>>(fea, w1T, b1, nullptr,
                                                        s2, MROWS, 256, 256, 1);
        gemm_k<false><<<dim3(4, 128), 256, GEMM_SMEM>>>(s2, w2T, b2, fea,
                                                        s1, MROWS, 256, 256, 0);
        ln_k<<<MROWS, 256>>>(s1, nfg, nfb, featT, words, s);
    }

    wtr_k<<<dim3(32, 8, NB), 256>>>(featT, (float*)d_out, 1024, 256,
                                    (long)1024 * 256, (long)256 * 1024, 0);
    (void)in_sizes; (void)n_in; (void)out_size;
}

// round 10
// speedup vs baseline: 2.6236x; 1.2359x over previous
#include <cuda_runtime.h>
#include <math.h>
#include <stdint.h>

#define NB    16
#define PTOT  1024
#define CD    256
#define HND   512
#define SEQL  20
#define MROWS (NB*PTOT)        /* 16384 */
#define KCONV 2304             /* 9 taps * 256 ch */

/* ---------------- scratch (device globals; no allocation allowed) -------- */
__device__ float g_featT [MROWS*CD];
__device__ float g_base  [MROWS*CD];
__device__ float g_t     [MROWS*CD];
__device__ float g_fea   [MROWS*CD];
__device__ float g_s1    [MROWS*CD];
__device__ float g_s2    [MROWS*CD];
__device__ float g_kv    [MROWS*2*CD];
__device__ float g_wConvT[KCONV*CD];
__device__ float g_wkvT  [CD*2*CD];
__device__ float g_woT   [CD*CD];
__device__ float g_w1T   [CD*CD];
__device__ float g_w2T   [CD*CD];
__device__ float g_hnTap [NB*CD*9];
__device__ float g_sconv [PTOT*CD];
__device__ float g_qhall [SEQL*NB*CD];
__device__ float g_qall  [SEQL*NB*CD];

/* ---------------- tf32 round helper (precompute only) -------------------- */
__device__ __forceinline__ float ftf32(float x)
{
    uint32_t u;
    asm("cvt.rna.tf32.f32 %0, %1;" : "=r"(u) : "f"(x));
    return __uint_as_float(u);
}

/* ---------------- cp.async helpers --------------------------------------- */
__device__ __forceinline__ void cp16(uint32_t d, const void* s, int sz)
{
    asm volatile("cp.async.cg.shared.global [%0], [%1], 16, %2;"
                 :: "r"(d), "l"(s), "r"(sz));
}
#define CP_COMMIT() asm volatile("cp.async.commit_group;")
#define CP_WAIT(n)  asm volatile("cp.async.wait_group %0;" :: "n"(n))

/* ---------------- generic 32x32 tiled transpose: dst[c][o] = src[o][c] --- */
__global__ void wtr_k(const float* __restrict__ src, float* __restrict__ dst,
                      int O, int Cc, long sStride, long dStride, int rnd)
{
    src += (size_t)blockIdx.z * sStride;
    dst += (size_t)blockIdx.z * dStride;
    __shared__ float tile[32][33];
    int o0 = blockIdx.x * 32, c0 = blockIdx.y * 32;
    int lx = threadIdx.x & 31, ly = threadIdx.x >> 5;
    #pragma unroll
    for (int i = ly; i < 32; i += 8)
        if (o0 + i < O && c0 + lx < Cc)
            tile[i][lx] = src[(size_t)(o0 + i) * Cc + c0 + lx];
    __syncthreads();
    #pragma unroll
    for (int i = ly; i < 32; i += 8)
        if (c0 + i < Cc && o0 + lx < O) {
            float v = tile[lx][i];
            dst[(size_t)(c0 + i) * O + o0 + lx] = rnd ? ftf32(v) : v;
        }
}

/* ---------------- conv weight relayout: [o][c][tap] -> [tap*256+c][o] ---- */
__global__ void wconv_k(const float* __restrict__ mw, float* __restrict__ dst)
{
    int k = blockIdx.x;
    int tap = k >> 8, c = k & 255;
    int o = threadIdx.x;
    dst[(size_t)k * CD + o] = ftf32(mw[((size_t)o * 776 + c) * 9 + tap]);
}

/* ---------------- hn tap sums -------------------------------------------- */
__global__ void hntap_k(const float* __restrict__ hn, const float* __restrict__ mw,
                        float* __restrict__ out)
{
    int n = blockIdx.x, o = threadIdx.x;
    __shared__ float h[HND];
    for (int i = o; i < HND; i += CD) h[i] = hn[(size_t)n * HND + i];
    __syncthreads();
    float acc[9];
    #pragma unroll
    for (int t = 0; t < 9; t++) acc[t] = 0.f;
    const float* wb = mw + ((size_t)o * 776 + 264) * 9;
    for (int c = 0; c < HND; c++) {
        float hv = h[c];
        #pragma unroll
        for (int t = 0; t < 9; t++) acc[t] += hv * wb[c * 9 + t];
    }
    #pragma unroll
    for (int t = 0; t < 9; t++) out[((size_t)n * CD + o) * 9 + t] = acc[t];
}

/* ---------------- spatial conv (invariant) ------------------------------- */
__global__ void sconv_k(const float* __restrict__ mw, float* __restrict__ out)
{
    int p = blockIdx.x, o = threadIdx.x;
    int h = p >> 5, w = p & 31;
    float acc = 0.f;
    const float* wb = mw + ((size_t)o * 776 + 256) * 9;
    for (int ky = 0; ky < 3; ky++) {
        int hh = h + ky - 1; if ((unsigned)hh >= 32u) continue;
        for (int kx = 0; kx < 3; kx++) {
            int ww = w + kx - 1; if ((unsigned)ww >= 32u) continue;
            float xmin = ww * (1.f/16.f) - 1.f, ymin = hh * (1.f/16.f) - 1.f;
            float xmax = (ww + 1) * (1.f/16.f) - 1.f, ymax = (hh + 1) * (1.f/16.f) - 1.f;
            float f[8] = {xmin, ymin, xmax, ymax,
                          0.5f*(xmin+xmax), 0.5f*(ymin+ymax), 1.f/32.f, 1.f/32.f};
            int t = ky * 3 + kx;
            #pragma unroll
            for (int c = 0; c < 8; c++) acc += f[c] * wb[c * 9 + t];
        }
    }
    out[(size_t)p * CD + o] = acc;
}

/* ---------------- base[n][p][o] = sconv + border-case hn taps ------------ */
__global__ void base_k(const float* __restrict__ sc, const float* __restrict__ ht,
                       float* __restrict__ base)
{
    int idx = blockIdx.x;
    int n = idx >> 10, p = idx & 1023;
    int o = threadIdx.x;
    int h = p >> 5, w = p & 31;
    int ky0 = (h == 0) ? 1 : 0, ky1 = (h == 31) ? 1 : 2;
    int kx0 = (w == 0) ? 1 : 0, kx1 = (w == 31) ? 1 : 2;
    const float* hb = ht + ((size_t)n * CD + o) * 9;
    float acc = sc[(size_t)p * CD + o];
    for (int ky = ky0; ky <= ky1; ky++)
        for (int kx = kx0; kx <= kx1; kx++)
            acc += hb[ky * 3 + kx];
    base[(size_t)idx * CD + o] = acc;
}

/* ---------------- q = relu(emb @ qconv_w^T + qconv_b), all steps --------- */
__global__ void qa_k(const float* __restrict__ emb, const float* __restrict__ qw,
                     const float* __restrict__ qb, float* __restrict__ qa)
{
    int s = blockIdx.x, n = blockIdx.y, tid = threadIdx.x;
    __shared__ float e[304];
    for (int i = tid; i < 300; i += CD) e[i] = emb[((size_t)n * SEQL + s) * 300 + i];
    __syncthreads();
    float acc = qb[tid];
    const float* wr = qw + (size_t)tid * 300;
    for (int i = 0; i < 300; i++) acc += e[i] * wr[i];
    qa[((size_t)s * NB + n) * CD + tid] = fmaxf(acc, 0.f);
}

/* ---------------- qh = q @ Wq^T + bq ------------------------------------- */
__global__ void qh_k(const float* __restrict__ qa, const float* __restrict__ ipw,
                     const float* __restrict__ ipb, float* __restrict__ qh)
{
    int s = blockIdx.x, n = blockIdx.y, tid = threadIdx.x;
    __shared__ float q[CD];
    q[tid] = qa[((size_t)s * NB + n) * CD + tid];
    __syncthreads();
    float acc = ipb[tid];
    const float* wr = ipw + (size_t)tid * CD;
    #pragma unroll 4
    for (int i = 0; i < CD; i++) acc += q[i] * wr[i];
    qh[((size_t)s * NB + n) * CD + tid] = acc;
}

/* =================== tf32 tensor-core GEMM, 128x128 tile, cp.async =======
   CTA 128x128, BK=32, 2 stages, 256 thr = 8 warps (4M x 2N),
   warp tile 32x64 = 2x8 m16n8k8 frags, fp32 accum.                        */
#define AS_STRIDE 36
#define BS_STRIDE 136            /* == 8 mod 32: conflict-free frag loads */
#define ASTG (128*AS_STRIDE)
#define STG_ELEMS (ASTG + 32*BS_STRIDE)   /* 8960 floats per stage */
#define GEMM_SMEM (2*STG_ELEMS*4)         /* 71680 bytes */

#define MMA_TF32(d, a, b) \
    asm volatile("mma.sync.aligned.m16n8k8.row.col.f32.tf32.tf32.f32 " \
                 "{%0,%1,%2,%3}, {%4,%5,%6,%7}, {%8,%9}, {%0,%1,%2,%3};" \
                 : "+f"(d[0]), "+f"(d[1]), "+f"(d[2]), "+f"(d[3]) \
                 : "r"(a[0]), "r"(a[1]), "r"(a[2]), "r"(a[3]), \
                   "r"(b[0]), "r"(b[1]))

template<bool CONV>
__device__ __forceinline__ void load_stage(float* stg, const float* A, const float* B,
                                           int m0, int n0, int k0, int K, int Nout, int tid)
{
    /* A tile 128x32 = 1024 x 16B chunks, 4 per thread */
    #pragma unroll
    for (int pass = 0; pass < 4; pass++) {
        int idx = pass * 256 + tid;
        int row = idx >> 3;
        int k4  = (idx & 7) << 2;
        const float* src;
        int sz = 16;
        if (!CONV) {
            src = A + (size_t)(m0 + row) * K + k0 + k4;
        } else {
            int k = k0 + k4;
            int tap = k >> 8;
            int c = k & 255;
            int dy = tap / 3 - 1, dx = tap % 3 - 1;
            int r = m0 + row;
            int p = r & 1023;
            int h = (p >> 5) + dy, w = (p & 31) + dx;
            if ((unsigned)h < 32u && (unsigned)w < 32u) {
                src = A + (size_t)((r & ~1023) | (h << 5) | w) * 256 + c;
            } else { src = A; sz = 0; }    /* zero-fill */
        }
        cp16((uint32_t)__cvta_generic_to_shared(stg + row * AS_STRIDE + k4), src, sz);
    }
    /* B tile 32x128 = 1024 x 16B chunks, 4 per thread */
    float* bs = stg + ASTG;
    #pragma unroll
    for (int pass = 0; pass < 4; pass++) {
        int idx = pass * 256 + tid;
        int kk = idx >> 5;
        int nn = (idx & 31) << 2;
        cp16((uint32_t)__cvta_generic_to_shared(bs + kk * BS_STRIDE + nn),
             B + (size_t)(k0 + kk) * Nout + n0 + nn, 16);
    }
    CP_COMMIT();
}

template<bool CONV>
__global__ void __launch_bounds__(256, 2)
gemm_k(const float* __restrict__ A, const float* __restrict__ B,
       const float* __restrict__ bias, const float* __restrict__ extra,
       float* __restrict__ C, int M, int Nout, int K, int doRelu)
{
    extern __shared__ float sm[];
    int tid  = threadIdx.x;
    int m0   = blockIdx.y * 128;
    int n0   = blockIdx.x * 128;
    int warp = tid >> 5;
    int lane = tid & 31;
    int wM = warp & 3;              /* M offset 32*wM */
    int wN = warp >> 2;             /* N offset 64*wN */
    int gid = lane >> 2;
    int tig = lane & 3;

    float acc[2][8][4];
    #pragma unroll
    for (int i = 0; i < 2; i++)
        #pragma unroll
        for (int j = 0; j < 8; j++)
            #pragma unroll
            for (int r = 0; r < 4; r++) acc[i][j][r] = 0.f;

    int nk = K >> 5;
    load_stage<CONV>(sm, A, B, m0, n0, 0, K, Nout, tid);

    for (int ki = 0; ki < nk; ki++) {
        float* As = sm + (ki & 1) * STG_ELEMS;
        float* Bs = As + ASTG;
        if (ki + 1 < nk) {
            load_stage<CONV>(sm + ((ki + 1) & 1) * STG_ELEMS, A, B,
                             m0, n0, (ki + 1) << 5, K, Nout, tid);
            CP_WAIT(1);
        } else {
            CP_WAIT(0);
        }
        __syncthreads();

        #pragma unroll
        for (int ks = 0; ks < 4; ks++) {
            int kb = ks << 3;
            uint32_t a[2][4], b[8][2];
            #pragma unroll
            for (int mf = 0; mf < 2; mf++) {
                int row = wM * 32 + mf * 16 + gid;
                const float* ap = As + row * AS_STRIDE + kb;
                a[mf][0] = __float_as_uint(ap[tig]);
                a[mf][1] = __float_as_uint(ap[8 * AS_STRIDE + tig]);
                a[mf][2] = __float_as_uint(ap[tig + 4]);
                a[mf][3] = __float_as_uint(ap[8 * AS_STRIDE + tig + 4]);
            }
            #pragma unroll
            for (int nf = 0; nf < 8; nf++) {
                int col = wN * 64 + nf * 8 + gid;
                b[nf][0] = __float_as_uint(Bs[(kb + tig) * BS_STRIDE + col]);
                b[nf][1] = __float_as_uint(Bs[(kb + tig + 4) * BS_STRIDE + col]);
            }
            #pragma unroll
            for (int mf = 0; mf < 2; mf++)
                #pragma unroll
                for (int nf = 0; nf < 8; nf++)
                    MMA_TF32(acc[mf][nf], a[mf], b[nf]);
        }
        __syncthreads();
    }

    /* epilogue */
    #pragma unroll
    for (int mf = 0; mf < 2; mf++) {
        int row = m0 + wM * 32 + mf * 16 + gid;
        #pragma unroll
        for (int nf = 0; nf < 8; nf++) {
            int col = n0 + wN * 64 + nf * 8 + 2 * tig;
            float2 v0 = make_float2(acc[mf][nf][0], acc[mf][nf][1]);
            float2 v1 = make_float2(acc[mf][nf][2], acc[mf][nf][3]);
            if (bias) {
                float2 bb = *reinterpret_cast<const float2*>(bias + col);
                v0.x += bb.x; v0.y += bb.y; v1.x += bb.x; v1.y += bb.y;
            }
            if (extra) {
                float2 e0 = *reinterpret_cast<const float2*>(extra + (size_t)row * Nout + col);
                float2 e1 = *reinterpret_cast<const float2*>(extra + (size_t)(row + 8) * Nout + col);
                v0.x += e0.x; v0.y += e0.y; v1.x += e1.x; v1.y += e1.y;
            }
            if (doRelu) {
                v0.x = fmaxf(v0.x, 0.f); v0.y = fmaxf(v0.y, 0.f);
                v1.x = fmaxf(v1.x, 0.f); v1.y = fmaxf(v1.y, 0.f);
            }
            *reinterpret_cast<float2*>(C + (size_t)row * Nout + col) = v0;
            *reinterpret_cast<float2*>(C + (size_t)(row + 8) * Nout + col) = v1;
        }
    }
}

/* ---------------- layernorm, warp-per-row (8 rows / block) --------------- */
__global__ void ln_k(const float* __restrict__ X, const float* __restrict__ g,
                     const float* __restrict__ b, float* __restrict__ Y,
                     const int* __restrict__ words, int step)
{
    if (words && words[step] == 0) return;     /* inactive: keep old state */
    int row  = blockIdx.x * 8 + (threadIdx.x >> 5);
    int lane = threadIdx.x & 31;
    const float* xr = X + (size_t)row * CD;
    float4 u = *reinterpret_cast<const float4*>(xr + lane * 4);
    float4 w = *reinterpret_cast<const float4*>(xr + 128 + lane * 4);
    float s  = u.x + u.y + u.z + u.w + w.x + w.y + w.z + w.w;
    float ss = u.x*u.x + u.y*u.y + u.z*u.z + u.w*u.w
             + w.x*w.x + w.y*w.y + w.z*w.z + w.w*w.w;
    #pragma unroll
    for (int off = 16; off; off >>= 1) {
        s  += __shfl_xor_sync(0xffffffffu, s, off);
        ss += __shfl_xor_sync(0xffffffffu, ss, off);
    }
    float mean = s * (1.f / 256.f);
    float var  = ss * (1.f / 256.f) - mean * mean;
    float inv  = rsqrtf(var + 1e-5f);
    float4 g0 = *reinterpret_cast<const float4*>(g + lane * 4);
    float4 g1 = *reinterpret_cast<const float4*>(g + 128 + lane * 4);
    float4 b0 = *reinterpret_cast<const float4*>(b + lane * 4);
    float4 b1 = *reinterpret_cast<const float4*>(b + 128 + lane * 4);
    float4 y0, y1;
    y0.x = (u.x - mean) * inv * g0.x + b0.x;
    y0.y = (u.y - mean) * inv * g0.y + b0.y;
    y0.z = (u.z - mean) * inv * g0.z + b0.z;
    y0.w = (u.w - mean) * inv * g0.w + b0.w;
    y1.x = (w.x - mean) * inv * g1.x + b1.x;
    y1.y = (w.y - mean) * inv * g1.y + b1.y;
    y1.z = (w.z - mean) * inv * g1.z + b1.z;
    y1.w = (w.w - mean) * inv * g1.w + b1.w;
    float* yr = Y + (size_t)row * CD;
    *reinterpret_cast<float4*>(yr + lane * 4) = y0;
    *reinterpret_cast<float4*>(yr + 128 + lane * 4) = y1;
}

/* ---------------- attention: per (p, head), 16x16 over batch ------------- */
__global__ void attn_k(const float* __restrict__ kv, const float* __restrict__ qh,
                       float* __restrict__ obuf, int step)
{
    int p = blockIdx.x, hd = blockIdx.y;
    int tid = threadIdx.x;
    __shared__ float qs[16][128], ks[16][128], vs[16][128], at[16][17];
    const float* qbase = qh + (size_t)step * NB * CD + hd * 128;
    for (int i = tid; i < 16 * 128; i += 256) {
        int l = i >> 7, d = i & 127;
        qs[l][d] = qbase[(size_t)l * CD + d];
        ks[l][d] = kv[(((size_t)l << 10) + p) * 512 + hd * 128 + d];
        vs[l][d] = kv[(((size_t)l << 10) + p) * 512 + 256 + hd * 128 + d];
    }
    __syncthreads();
    {
        int l = tid >> 4, m = tid & 15;
        float s = 0.f;
        #pragma unroll 8
        for (int d = 0; d < 128; d++) s += qs[l][d] * ks[m][d];
        s *= 0.08838834764831845f;
        float mx = s;
        #pragma unroll
        for (int off = 8; off; off >>= 1) mx = fmaxf(mx, __shfl_xor_sync(0xffffffffu, mx, off));
        float e = expf(s - mx);
        float sum = e;
        #pragma unroll
        for (int off = 8; off; off >>= 1) sum += __shfl_xor_sync(0xffffffffu, sum, off);
        at[l][m] = e / sum;
    }
    __syncthreads();
    {
        int l = tid >> 4;
        int d0 = (tid & 15) * 8;
        float acc[8];
        #pragma unroll
        for (int j = 0; j < 8; j++) acc[j] = 0.f;
        #pragma unroll
        for (int m = 0; m < 16; m++) {
            float a = at[l][m];
            #pragma unroll
            for (int j = 0; j < 8; j++) acc[j] += a * vs[m][d0 + j];
        }
        float* o = obuf + (((size_t)l << 10) + p) * CD + hd * 128 + d0;
        #pragma unroll
        for (int j = 0; j < 8; j++) o[j] = acc[j];
    }
}

/* ======================================================================== */
extern "C" void kernel_launch(void* const* d_in, const int* in_sizes, int n_in,
                              void* d_out, int out_size)
{
    const float* hn      = (const float*)d_in[1];
    const float* feature = (const float*)d_in[2];
    const float* emb     = (const float*)d_in[3];
    const int*   words   = (const int*)  d_in[4];
    const float* qw      = (const float*)d_in[5];
    const float* qb      = (const float*)d_in[6];
    const float* mw      = (const float*)d_in[7];
    const float* mg      = (const float*)d_in[8];
    const float* mb      = (const float*)d_in[9];
    const float* ipw     = (const float*)d_in[10];
    const float* ipb     = (const float*)d_in[11];
    const float* opw     = (const float*)d_in[12];
    const float* opb     = (const float*)d_in[13];
    const float* ng      = (const float*)d_in[14];
    const float* nbv     = (const float*)d_in[15];
    const float* w1      = (const float*)d_in[16];
    const float* b1      = (const float*)d_in[17];
    const float* w2      = (const float*)d_in[18];
    const float* b2      = (const float*)d_in[19];
    const float* nfg     = (const float*)d_in[20];
    const float* nfb     = (const float*)d_in[21];

    float *featT, *base, *t, *fea, *s1, *s2, *kvb;
    float *wConvT, *wkvT, *woT, *w1T, *w2T, *hnTap, *sconv, *qhall, *qall;
    cudaGetSymbolAddress((void**)&featT, g_featT);
    cudaGetSymbolAddress((void**)&base,  g_base);
    cudaGetSymbolAddress((void**)&t,     g_t);
    cudaGetSymbolAddress((void**)&fea,   g_fea);
    cudaGetSymbolAddress((void**)&s1,    g_s1);
    cudaGetSymbolAddress((void**)&s2,    g_s2);
    cudaGetSymbolAddress((void**)&kvb,   g_kv);
    cudaGetSymbolAddress((void**)&wConvT,g_wConvT);
    cudaGetSymbolAddress((void**)&wkvT,  g_wkvT);
    cudaGetSymbolAddress((void**)&woT,   g_woT);
    cudaGetSymbolAddress((void**)&w1T,   g_w1T);
    cudaGetSymbolAddress((void**)&w2T,   g_w2T);
    cudaGetSymbolAddress((void**)&hnTap, g_hnTap);
    cudaGetSymbolAddress((void**)&sconv, g_sconv);
    cudaGetSymbolAddress((void**)&qhall, g_qhall);
    cudaGetSymbolAddress((void**)&qall,  g_qall);

    cudaFuncSetAttribute(gemm_k<true>,  cudaFuncAttributeMaxDynamicSharedMemorySize, GEMM_SMEM);
    cudaFuncSetAttribute(gemm_k<false>, cudaFuncAttributeMaxDynamicSharedMemorySize, GEMM_SMEM);

    /* ---- precompute ---- */
    wtr_k<<<dim3(8, 32, NB), 256>>>(feature, featT, 256, 1024,
                                    (long)256 * 1024, (long)1024 * 256, 0);
    wconv_k<<<KCONV, 256>>>(mw, wConvT);
    wtr_k<<<dim3(16, 8, 1), 256>>>(ipw + 256 * 256, wkvT, 512, 256, 0, 0, 1);
    wtr_k<<<dim3(8, 8, 1), 256>>>(opw, woT, 256, 256, 0, 0, 1);
    wtr_k<<<dim3(8, 8, 1), 256>>>(w1, w1T, 256, 256, 0, 0, 1);
    wtr_k<<<dim3(8, 8, 1), 256>>>(w2, w2T, 256, 256, 0, 0, 1);
    hntap_k<<<NB, 256>>>(hn, mw, hnTap);
    sconv_k<<<PTOT, 256>>>(mw, sconv);
    base_k<<<MROWS, 256>>>(sconv, hnTap, base);
    qa_k<<<dim3(SEQL, NB), 256>>>(emb, qw, qb, qall);
    qh_k<<<dim3(SEQL, NB), 256>>>(qall, ipw, ipb, qhall);

    /* ---- 20 recurrent steps ---- */
    for (int s = 0; s < SEQL; s++) {
        gemm_k<true><<<dim3(2, 128), 256, GEMM_SMEM>>>(featT, wConvT, nullptr, base,
                                                       s1, MROWS, 256, KCONV, 1);
        ln_k<<<2048, 256>>>(s1, mg, mb, t, nullptr, 0);
        gemm_k<false><<<dim3(4, 128), 256, GEMM_SMEM>>>(t, wkvT, ipb + 256, nullptr,
                                                        kvb, MROWS, 512, 256, 0);
        attn_k<<<dim3(PTOT, 2), 256>>>(kvb, qhall, s2, s);
        gemm_k<false><<<dim3(2, 128), 256, GEMM_SMEM>>>(s2, woT, opb, t,
                                                        s1, MROWS, 256, 256, 0);
        ln_k<<<2048, 256>>>(s1, ng, nbv, fea, nullptr, 0);
        gemm_k<false><<<dim3(2, 128), 256, GEMM_SMEM>>>(fea, w1T, b1, nullptr,
                                                        s2, MROWS, 256, 256, 1);
        gemm_k<false><<<dim3(2, 128), 256, GEMM_SMEM>>>(s2, w2T, b2, fea,
                                                        s1, MROWS, 256, 256, 0);
        ln_k<<<2048, 256>>>(s1, nfg, nfb, featT, words, s);
    }

    wtr_k<<<dim3(32, 8, NB), 256>>>(featT, (float*)d_out, 1024, 256,
                                    (long)1024 * 256, (long)256 * 1024, 0);
    (void)in_sizes; (void)n_in; (void)out_size;
}